// round 4
// baseline (speedup 1.0000x reference)
#include <cuda_runtime.h>
#include <cstdint>

// ChessboardLayer: (B,H,W,C)=(32,256,256,32) fp32 space-to-depth into 8x8 cells.
// Pure 4KiB-block transpose:
//   in  chunk id q = ((b*8+r)*32 + i)*8 + c   (q = br*256 + i*8 + c)
//   out chunk id   = br*256 + c*32 + i
//
// R3: 8 chunks per CTA, base = blk*8 -> chunks share (br, i), c = k (0..7).
//   read : 32 KiB fully contiguous
//   write: 8 x 4 KiB contiguous streams, stride 32 KiB
// Two front-batched load groups of 4 (MLP=4, regs<=40, occ 8/SM).

__global__ void __launch_bounds__(256, 8)
chessboard_kernel(const float4* __restrict__ in, float4* __restrict__ out) {
    unsigned blk = blockIdx.x;           // = q >> 3 for all 8 chunks
    unsigned t   = threadIdx.x;

    unsigned i  = blk & 31u;
    unsigned br = blk >> 5;

    const float4* ib = in  + (size_t)blk * 2048u + t;              // 8 chunks * 256 f4
    float4*       ob = out + (size_t)(br * 256u + i) * 256u + t;   // + k*8192

    // k = 0..3
    float4 v0 = __ldcs(ib + 0u * 256u);
    float4 v1 = __ldcs(ib + 1u * 256u);
    float4 v2 = __ldcs(ib + 2u * 256u);
    float4 v3 = __ldcs(ib + 3u * 256u);
    __stcs(ob + 0u * 8192u, v0);
    __stcs(ob + 1u * 8192u, v1);
    __stcs(ob + 2u * 8192u, v2);
    __stcs(ob + 3u * 8192u, v3);

    // k = 4..7
    float4 v4 = __ldcs(ib + 4u * 256u);
    float4 v5 = __ldcs(ib + 5u * 256u);
    float4 v6 = __ldcs(ib + 6u * 256u);
    float4 v7 = __ldcs(ib + 7u * 256u);
    __stcs(ob + 4u * 8192u, v4);
    __stcs(ob + 5u * 8192u, v5);
    __stcs(ob + 6u * 8192u, v6);
    __stcs(ob + 7u * 8192u, v7);
}

extern "C" void kernel_launch(void* const* d_in, const int* in_sizes, int n_in,
                              void* d_out, int out_size) {
    const float4* in  = (const float4*)d_in[0];
    float4*       out = (float4*)d_out;
    // 65536 chunks / 8 per CTA = 8192 CTAs
    chessboard_kernel<<<8192, 256>>>(in, out);
}